// round 1
// baseline (speedup 1.0000x reference)
#include <cuda_runtime.h>
#include <math.h>

// Problem constants
#define BATCH 8
#define HH 256
#define WW 256
#define GY 512
#define GX 512
#define JJ 7
#define NS 100000

// Scratch: device globals (allocation is forbidden)
__device__ float2 g_tmp[BATCH * HH * GX];        // [b][y][kx]   (8 MB)
__device__ float2 g_ghat[GY * GX * BATCH];       // [ky][kx][b]  (16 MB) batch-innermost for gather

__device__ __forceinline__ int brev9(int k) { return (int)(__brev((unsigned)k) >> 23); }

// ---------------------------------------------------------------------------
// Shared-memory 512-point radix-2 DIF FFT. 256 threads, each does one
// butterfly per stage. Output read out in bit-reversed order.
// ---------------------------------------------------------------------------
__device__ __forceinline__ void fft512(float2* sh, int t) {
    #pragma unroll
    for (int span = 256; span >= 1; span >>= 1) {
        __syncthreads();
        int j = t & (span - 1);
        int idx0 = 2 * t - j;          // (t/span)*2*span + j
        int idx1 = idx0 + span;
        float ang = (-(float)M_PI) * (float)j / (float)span;
        float s, c;
        __sincosf(ang, &s, &c);        // fast-math sincos; |err| ~1e-6 relative, fine for 1e-3 tol
        float2 a = sh[idx0];
        float2 b = sh[idx1];
        float2 d = make_float2(a.x - b.x, a.y - b.y);
        sh[idx0] = make_float2(a.x + b.x, a.y + b.y);
        sh[idx1] = make_float2(d.x * c - d.y * s, d.x * s + d.y * c);
    }
    __syncthreads();
}

// ---------------------------------------------------------------------------
// Stage A: apodize + row FFT (along x). One block per (y, b).
// Input rows have 256 nonzero entries; zero-pad to 512.
// Folds ortho norm 1/512 into the load.
// ---------------------------------------------------------------------------
__global__ void __launch_bounds__(256) row_fft_kernel(
    const float* __restrict__ xr, const float* __restrict__ xi,
    const float* __restrict__ scy, const float* __restrict__ scx)
{
    __shared__ float2 sh[GX];
    int y = blockIdx.x;
    int b = blockIdx.y;
    int t = threadIdx.x;

    float sy = scy[y] * (1.0f / 512.0f);   // fold ortho 1/sqrt(GY*GX)
    const float* rr = xr + ((size_t)b * HH + y) * WW;
    const float* ii = xi + ((size_t)b * HH + y) * WW;
    float s = sy * scx[t];
    sh[t]       = make_float2(rr[t] * s, ii[t] * s);
    sh[t + 256] = make_float2(0.f, 0.f);

    fft512(sh, t);

    float2* out = g_tmp + ((size_t)b * HH + y) * GX;
    out[t]       = sh[brev9(t)];
    out[t + 256] = sh[brev9(t + 256)];
}

// ---------------------------------------------------------------------------
// Stage B: column FFT (along y). One block per (x, b).
// Columns have 256 nonzero entries (rows 0..255 of tmp). Writes ghat with
// batch-innermost layout for the gather.
// ---------------------------------------------------------------------------
__global__ void __launch_bounds__(256) col_fft_kernel()
{
    __shared__ float2 sh[GY];
    int x = blockIdx.x;
    int b = blockIdx.y;
    int t = threadIdx.x;

    const float2* col = g_tmp + (size_t)b * HH * GX + x;
    sh[t]       = col[(size_t)t * GX];
    sh[t + 256] = make_float2(0.f, 0.f);

    fft512(sh, t);

    int k0 = t, k1 = t + 256;
    g_ghat[((size_t)k0 * GX + x) * BATCH + b] = sh[brev9(k0)];
    g_ghat[((size_t)k1 * GX + x) * BATCH + b] = sh[brev9(k1)];
}

// ---------------------------------------------------------------------------
// Stage C: KB 7x7 gather + phase. One thread per sample, all 8 batches in
// registers. Each tap = 64 B contiguous (8 complex, batch-innermost) = 4x
// float4; whole spectrum (16 MB) lives in L2.
// ---------------------------------------------------------------------------
__global__ void __launch_bounds__(256) gather_kernel(
    const float* __restrict__ wy, const float* __restrict__ wx,
    const float* __restrict__ phr, const float* __restrict__ phi,
    const int* __restrict__ iy, const int* __restrict__ ix,
    float* __restrict__ out)
{
    int n = blockIdx.x * blockDim.x + threadIdx.x;
    if (n >= NS) return;

    int   iyv[JJ], ixv[JJ];
    float wyv[JJ], wxv[JJ];
    #pragma unroll
    for (int j = 0; j < JJ; j++) {
        iyv[j] = iy[(size_t)n * JJ + j];
        ixv[j] = ix[(size_t)n * JJ + j];
        wyv[j] = wy[(size_t)n * JJ + j];
        wxv[j] = wx[(size_t)n * JJ + j];
    }

    float2 acc[BATCH];
    #pragma unroll
    for (int b = 0; b < BATCH; b++) acc[b] = make_float2(0.f, 0.f);

    #pragma unroll
    for (int j = 0; j < JJ; j++) {
        const float2* rowp = g_ghat + (size_t)iyv[j] * GX * BATCH;
        float wj = wyv[j];
        #pragma unroll
        for (int k = 0; k < JJ; k++) {
            float w = wj * wxv[k];
            const float4* p = (const float4*)(rowp + (size_t)ixv[k] * BATCH);
            float4 v0 = p[0], v1 = p[1], v2 = p[2], v3 = p[3];
            acc[0].x += w * v0.x; acc[0].y += w * v0.y;
            acc[1].x += w * v0.z; acc[1].y += w * v0.w;
            acc[2].x += w * v1.x; acc[2].y += w * v1.y;
            acc[3].x += w * v1.z; acc[3].y += w * v1.w;
            acc[4].x += w * v2.x; acc[4].y += w * v2.y;
            acc[5].x += w * v2.z; acc[5].y += w * v2.w;
            acc[6].x += w * v3.x; acc[6].y += w * v3.y;
            acc[7].x += w * v3.z; acc[7].y += w * v3.w;
        }
    }

    float pr = phr[n], pi = phi[n];
    #pragma unroll
    for (int b = 0; b < BATCH; b++) {
        float re = acc[b].x * pr - acc[b].y * pi;
        float im = acc[b].x * pi + acc[b].y * pr;
        out[((size_t)b * NS + n) * 2 + 0] = re;
        out[((size_t)b * NS + n) * 2 + 1] = im;
    }
}

// ---------------------------------------------------------------------------
// kernel_launch: inputs in metadata order:
// 0:xr 1:xi 2:sc_y 3:sc_x 4:wy 5:wx 6:phr 7:phi 8:iy 9:ix
// ---------------------------------------------------------------------------
extern "C" void kernel_launch(void* const* d_in, const int* in_sizes, int n_in,
                              void* d_out, int out_size)
{
    const float* xr  = (const float*)d_in[0];
    const float* xi  = (const float*)d_in[1];
    const float* scy = (const float*)d_in[2];
    const float* scx = (const float*)d_in[3];
    const float* wy  = (const float*)d_in[4];
    const float* wx  = (const float*)d_in[5];
    const float* phr = (const float*)d_in[6];
    const float* phi = (const float*)d_in[7];
    const int*   iy  = (const int*)d_in[8];
    const int*   ix  = (const int*)d_in[9];
    float* out = (float*)d_out;

    dim3 rowGrid(HH, BATCH);
    row_fft_kernel<<<rowGrid, 256>>>(xr, xi, scy, scx);

    dim3 colGrid(GX, BATCH);
    col_fft_kernel<<<colGrid, 256>>>();

    int gBlocks = (NS + 255) / 256;
    gather_kernel<<<gBlocks, 256>>>(wy, wx, phr, phi, iy, ix, out);
}

// round 3
// speedup vs baseline: 1.9977x; 1.9977x over previous
#include <cuda_runtime.h>
#include <math.h>

// Problem constants
#define BATCH 8
#define HH 256
#define WW 256
#define GY 512
#define GX 512
#define JJ 7
#define NS 100000

// Scratch (allocation is forbidden -> device globals)
// tmp : [y][kx][b]   256*512*8 float2 = 8 MB   (batch innermost = full 32B sectors)
// ghat: [ky][x][b]   512*512*8 float2 = 16 MB  (batch innermost = full 64B taps)
__device__ float2 g_tmp[HH * GX * BATCH];
__device__ float2 g_ghat[GY * GX * BATCH];

__device__ __forceinline__ int brev9(int k) { return (int)(__brev((unsigned)k) >> 23); }

#define SH_STRIDE 513   // pad to break inter-column bank alignment

// 4 simultaneous 512-pt radix-2 DIF FFTs; one twiddle sincos serves 4 butterflies.
__device__ __forceinline__ void fft512x4(float2 (*sh)[SH_STRIDE], int t) {
    #pragma unroll
    for (int span = 256; span >= 1; span >>= 1) {
        __syncthreads();
        int j = t & (span - 1);
        int idx0 = 2 * t - j;
        int idx1 = idx0 + span;
        float ang = (-(float)M_PI) * (float)j / (float)span;
        float s, c;
        __sincosf(ang, &s, &c);
        #pragma unroll
        for (int cc = 0; cc < 4; cc++) {
            float2 a = sh[cc][idx0];
            float2 b = sh[cc][idx1];
            float2 d = make_float2(a.x - b.x, a.y - b.y);
            sh[cc][idx0] = make_float2(a.x + b.x, a.y + b.y);
            sh[cc][idx1] = make_float2(d.x * c - d.y * s, d.x * s + d.y * c);
        }
    }
    __syncthreads();
}

// ---------------------------------------------------------------------------
// Stage A: apodize + row FFT. Block = (y, batch-group of 4).
// Writes tmp[y][kx][b] -> 32B-sector granular, coalesced.
// ---------------------------------------------------------------------------
__global__ void __launch_bounds__(256) row_fft_kernel(
    const float* __restrict__ xr, const float* __restrict__ xi,
    const float* __restrict__ scy, const float* __restrict__ scx)
{
    __shared__ float2 sh[4][SH_STRIDE];
    int y  = blockIdx.x;
    int bg = blockIdx.y;          // 0 or 1
    int t  = threadIdx.x;

    float s = scy[y] * (1.0f / 512.0f) * scx[t];   // fold ortho 1/sqrt(GY*GX)
    #pragma unroll
    for (int c = 0; c < 4; c++) {
        int b = bg * 4 + c;
        const float* rr = xr + ((size_t)b * HH + y) * WW;
        const float* ii = xi + ((size_t)b * HH + y) * WW;
        sh[c][t]       = make_float2(rr[t] * s, ii[t] * s);
        sh[c][t + 256] = make_float2(0.f, 0.f);
    }

    fft512x4(sh, t);

    // write [y][kx][b], b = bg*4 + c ; linear i = kx*4 + c -> coalesced
    float2* outp = g_tmp + (size_t)y * GX * BATCH + bg * 4;
    #pragma unroll
    for (int it = 0; it < 8; it++) {
        int i  = it * 256 + t;
        int kx = i >> 2;
        int c  = i & 3;
        outp[(size_t)kx * BATCH + c] = sh[c][brev9(kx)];
    }
}

// ---------------------------------------------------------------------------
// Stage B: col FFT. Block = (x, batch-group of 4).
// Reads tmp[y][x][b] (32B chunks), writes ghat[ky][x][b] (32B chunks).
// ---------------------------------------------------------------------------
__global__ void __launch_bounds__(256) col_fft_kernel()
{
    __shared__ float2 sh[4][SH_STRIDE];
    int x  = blockIdx.x;
    int bg = blockIdx.y;
    int t  = threadIdx.x;

    const float2* inp = g_tmp + (size_t)x * BATCH + bg * 4;
    #pragma unroll
    for (int it = 0; it < 4; it++) {
        int i = it * 256 + t;
        int y = i >> 2;
        int c = i & 3;
        sh[c][y]       = inp[(size_t)y * GX * BATCH + c];
        sh[c][y + 256] = make_float2(0.f, 0.f);
    }

    fft512x4(sh, t);

    float2* outp = g_ghat + (size_t)x * BATCH + bg * 4;
    #pragma unroll
    for (int it = 0; it < 8; it++) {
        int i  = it * 256 + t;
        int ky = i >> 2;
        int c  = i & 3;
        outp[(size_t)ky * GX * BATCH + c] = sh[c][brev9(ky)];
    }
}

// ---------------------------------------------------------------------------
// Stage C: gather. Lane = (sample, batch): 800k lanes, each accumulates one
// (n,b) over the 7x7 KB stencil with float2 loads. Warp-inst = 4 samples x
// 64B contiguous taps = 8 full sectors.
// ---------------------------------------------------------------------------
__global__ void __launch_bounds__(256) gather_kernel(
    const float* __restrict__ wy, const float* __restrict__ wx,
    const float* __restrict__ phr, const float* __restrict__ phi,
    const int* __restrict__ iy, const int* __restrict__ ix,
    float* __restrict__ out)
{
    int g = blockIdx.x * blockDim.x + threadIdx.x;
    if (g >= NS * BATCH) return;
    int n = g >> 3;
    int b = g & 7;

    int   ixv[JJ];
    float wxv[JJ];
    #pragma unroll
    for (int k = 0; k < JJ; k++) {
        ixv[k] = ix[(size_t)n * JJ + k];
        wxv[k] = wx[(size_t)n * JJ + k];
    }

    float accx = 0.f, accy = 0.f;
    #pragma unroll
    for (int j = 0; j < JJ; j++) {
        int   iyj = iy[(size_t)n * JJ + j];
        float wj  = wy[(size_t)n * JJ + j];
        const float2* rowp = g_ghat + (size_t)iyj * GX * BATCH + b;
        #pragma unroll
        for (int k = 0; k < JJ; k++) {
            float2 v = rowp[(size_t)ixv[k] * BATCH];
            float  w = wj * wxv[k];
            accx += w * v.x;
            accy += w * v.y;
        }
    }

    float pr = phr[n], pi = phi[n];
    float re = accx * pr - accy * pi;
    float im = accx * pi + accy * pr;
    float2* o = (float2*)(out + ((size_t)b * NS + n) * 2);
    *o = make_float2(re, im);
}

// ---------------------------------------------------------------------------
// inputs: 0:xr 1:xi 2:sc_y 3:sc_x 4:wy 5:wx 6:phr 7:phi 8:iy 9:ix
// ---------------------------------------------------------------------------
extern "C" void kernel_launch(void* const* d_in, const int* in_sizes, int n_in,
                              void* d_out, int out_size)
{
    const float* xr  = (const float*)d_in[0];
    const float* xi  = (const float*)d_in[1];
    const float* scy = (const float*)d_in[2];
    const float* scx = (const float*)d_in[3];
    const float* wy  = (const float*)d_in[4];
    const float* wx  = (const float*)d_in[5];
    const float* phr = (const float*)d_in[6];
    const float* phi = (const float*)d_in[7];
    const int*   iy  = (const int*)d_in[8];
    const int*   ix  = (const int*)d_in[9];
    float* out = (float*)d_out;

    dim3 rowGrid(HH, 2);
    row_fft_kernel<<<rowGrid, 256>>>(xr, xi, scy, scx);

    dim3 colGrid(GX, 2);
    col_fft_kernel<<<colGrid, 256>>>();

    int lanes = NS * BATCH;
    gather_kernel<<<(lanes + 255) / 256, 256>>>(wy, wx, phr, phi, iy, ix, out);
}